// round 2
// baseline (speedup 1.0000x reference)
#include <cuda_runtime.h>
#include <cuda_bf16.h>

// LightplaneSplatter: splat N rays x 72 samples x 16 channels into a
// (1,128,128,128,16) grid with trilinear weights, masking OOB corners.
//
// Inputs (metadata order):
//   d_in[0] directions  float32 [N,3]
//   d_in[1] origins     float32 [N,3]
//   d_in[2] near        float32 [N]
//   d_in[3] far         float32 [N]
//   d_in[4] encoding    float32 [N,16]
//   d_in[5] grid_idx    int32   [N]
// Output: float32 grid [1,128,128,128,16] flattened (33,554,432 elems).

#define GW 128
#define GH 128
#define GD 128
#define GC 16
#define NUM_SAMPLES 64
#define NUM_SAMPLES_INF 8
#define ST (NUM_SAMPLES + NUM_SAMPLES_INF)  // 72
#define DISPARITY_AT_INF 1e-4f

// block: x = 16 channels, y = 8 samples  (128 threads)
// grid:  x = 9 sample-chunks (9*8 = 72), y = N rays
__global__ void __launch_bounds__(128) splat_kernel(
    const float* __restrict__ dirs,
    const float* __restrict__ orig,
    const float* __restrict__ nearv,
    const float* __restrict__ farv,
    const float* __restrict__ enc,
    const int*   __restrict__ gidx,
    float* __restrict__ out)
{
    const int n  = blockIdx.y;
    const int si = blockIdx.x * blockDim.y + threadIdx.y;  // 0..71
    const int c  = threadIdx.x;                            // 0..15

    const float nr = nearv[n];
    const float fr = farv[n];

    float t;
    if (si < NUM_SAMPLES) {
        t = nr + (fr - nr) * (((float)si + 0.5f) * (1.0f / NUM_SAMPLES));
    } else {
        const float j    = (float)(si - NUM_SAMPLES + 1) * (1.0f / NUM_SAMPLES_INF);
        const float invf = 1.0f / fr;
        const float disp = invf + (DISPARITY_AT_INF - invf) * j;
        t = 1.0f / disp;
    }

    const float px = orig[n * 3 + 0] + t * dirs[n * 3 + 0];
    const float py = orig[n * 3 + 1] + t * dirs[n * 3 + 1];
    const float pz = orig[n * 3 + 2] + t * dirs[n * 3 + 2];

    // world [-1,1] -> voxel coords, align_corners=True
    const float vx = (px + 1.0f) * 0.5f * (float)(GW - 1);
    const float vy = (py + 1.0f) * 0.5f * (float)(GH - 1);
    const float vz = (pz + 1.0f) * 0.5f * (float)(GD - 1);

    const float bxf = floorf(vx);
    const float byf = floorf(vy);
    const float bzf = floorf(vz);

    // Any corner possibly in-bounds? corners are base and base+1, so need
    // base >= -1 and base <= size-1. Written so NaN also fails -> skip.
    const bool maybe_in =
        (bxf >= -1.0f) && (bxf <= (float)(GW - 1)) &&
        (byf >= -1.0f) && (byf <= (float)(GH - 1)) &&
        (bzf >= -1.0f) && (bzf <= (float)(GD - 1));
    if (!maybe_in) return;

    const float fx = vx - bxf;
    const float fy = vy - byf;
    const float fz = vz - bzf;
    const int bx = (int)bxf;
    const int by = (int)byf;
    const int bz = (int)bzf;

    const float e = enc[n * GC + c];
    const int   b = gidx[n];

    const float wx0 = 1.0f - fx, wx1 = fx;
    const float wy0 = 1.0f - fy, wy1 = fy;
    const float wz0 = 1.0f - fz, wz1 = fz;

#pragma unroll
    for (int k = 0; k < 8; k++) {
        const int dx = k & 1;
        const int dy = (k >> 1) & 1;
        const int dz = (k >> 2) & 1;
        const int ix = bx + dx;
        const int iy = by + dy;
        const int iz = bz + dz;
        if ((unsigned)ix < GW && (unsigned)iy < GH && (unsigned)iz < GD) {
            const float w = (dx ? wx1 : wx0) * (dy ? wy1 : wy0) * (dz ? wz1 : wz0);
            const long long flat =
                ((((long long)b * GD + iz) * GH + iy) * GW + ix) * GC + c;
            atomicAdd(out + flat, w * e);
        }
    }
}

extern "C" void kernel_launch(void* const* d_in, const int* in_sizes, int n_in,
                              void* d_out, int out_size)
{
    const float* dirs  = (const float*)d_in[0];
    const float* orig  = (const float*)d_in[1];
    const float* nearv = (const float*)d_in[2];
    const float* farv  = (const float*)d_in[3];
    const float* enc   = (const float*)d_in[4];
    const int*   gidx  = (const int*)  d_in[5];
    float* out = (float*)d_out;

    const int N = in_sizes[2];  // near has one element per ray

    cudaMemsetAsync(d_out, 0, (size_t)out_size * sizeof(float));

    dim3 block(16, 8, 1);            // 16 channels x 8 samples
    dim3 grid((ST + 7) / 8, N, 1);   // 9 sample-chunks x N rays
    splat_kernel<<<grid, block>>>(dirs, orig, nearv, farv, enc, gidx, out);
}

// round 3
// speedup vs baseline: 1.4404x; 1.4404x over previous
#include <cuda_runtime.h>
#include <cuda_bf16.h>

// LightplaneSplatter: splat N rays x 72 samples x 16 channels into a
// (1,128,128,128,16) grid with trilinear weights, masking OOB corners.
//
// Inputs (metadata order):
//   d_in[0] directions  float32 [N,3]
//   d_in[1] origins     float32 [N,3]
//   d_in[2] near        float32 [N]
//   d_in[3] far         float32 [N]
//   d_in[4] encoding    float32 [N,16]
//   d_in[5] grid_idx    int32   [N]
// Output: float32 grid [1,128,128,128,16] flattened (33,554,432 elems).

#define GW 128
#define GH 128
#define GD 128
#define GC 16
#define NUM_SAMPLES 64
#define NUM_SAMPLES_INF 8
#define ST (NUM_SAMPLES + NUM_SAMPLES_INF)  // 72
#define DISPARITY_AT_INF 1e-4f

// Strides in floats
#define SX (GC)            // 16
#define SY (GW * GC)       // 2048
#define SZ (GH * GW * GC)  // 262144

// Vectorized global reduction: 16B per lane, sm_90+.
__device__ __forceinline__ void red_add_v4(float* p, float4 v) {
    asm volatile("red.global.add.v4.f32 [%0], {%1, %2, %3, %4};"
                 :: "l"(p), "f"(v.x), "f"(v.y), "f"(v.z), "f"(v.w)
                 : "memory");
}

// block: x = 4 channel-groups (float4 each), y = 72 samples  (288 threads)
// grid:  x = N rays
__global__ void __launch_bounds__(288) splat_kernel(
    const float* __restrict__ dirs,
    const float* __restrict__ orig,
    const float* __restrict__ nearv,
    const float* __restrict__ farv,
    const float* __restrict__ enc,
    const int*   __restrict__ gidx,
    float* __restrict__ out)
{
    const int n  = blockIdx.x;
    const int si = threadIdx.y;   // 0..71
    const int c4 = threadIdx.x;   // 0..3  (channels 4*c4 .. 4*c4+3)

    const float nr = nearv[n];
    const float fr = farv[n];

    float t;
    if (si < NUM_SAMPLES) {
        t = nr + (fr - nr) * (((float)si + 0.5f) * (1.0f / NUM_SAMPLES));
    } else {
        const float j    = (float)(si - NUM_SAMPLES + 1) * (1.0f / NUM_SAMPLES_INF);
        const float invf = 1.0f / fr;
        const float disp = invf + (DISPARITY_AT_INF - invf) * j;
        t = 1.0f / disp;
    }

    const float px = orig[n * 3 + 0] + t * dirs[n * 3 + 0];
    const float py = orig[n * 3 + 1] + t * dirs[n * 3 + 1];
    const float pz = orig[n * 3 + 2] + t * dirs[n * 3 + 2];

    // world [-1,1] -> voxel coords, align_corners=True
    const float vx = (px + 1.0f) * 0.5f * (float)(GW - 1);
    const float vy = (py + 1.0f) * 0.5f * (float)(GH - 1);
    const float vz = (pz + 1.0f) * 0.5f * (float)(GD - 1);

    const float bxf = floorf(vx);
    const float byf = floorf(vy);
    const float bzf = floorf(vz);

    // Any corner possibly in-bounds? corners are base and base+1, so need
    // base >= -1 and base <= size-1. Written so NaN also fails -> skip.
    const bool maybe_in =
        (bxf >= -1.0f) && (bxf <= (float)(GW - 1)) &&
        (byf >= -1.0f) && (byf <= (float)(GH - 1)) &&
        (bzf >= -1.0f) && (bzf <= (float)(GD - 1));
    if (!maybe_in) return;

    const float fx = vx - bxf;
    const float fy = vy - byf;
    const float fz = vz - bzf;
    const int bx = (int)bxf;
    const int by = (int)byf;
    const int bz = (int)bzf;

    const int b = gidx[n];
    const float4 e = *reinterpret_cast<const float4*>(enc + n * GC + c4 * 4);

    const float wx0 = 1.0f - fx, wx1 = fx;
    const float wy0 = 1.0f - fy, wy1 = fy;
    const float wz0 = 1.0f - fz, wz1 = fz;

    // Base flat offset (may be "negative-corner"; only dereferenced in-bounds).
    const long long basef =
        ((((long long)b * GD + bz) * GH + by) * GW + bx) * GC + c4 * 4;

    const bool x0 = (unsigned)bx       < GW;
    const bool x1 = (unsigned)(bx + 1) < GW;
    const bool y0 = (unsigned)by       < GH;
    const bool y1 = (unsigned)(by + 1) < GH;
    const bool z0 = (unsigned)bz       < GD;
    const bool z1 = (unsigned)(bz + 1) < GD;

#pragma unroll
    for (int k = 0; k < 8; k++) {
        const int dx = k & 1;
        const int dy = (k >> 1) & 1;
        const int dz = (k >> 2) & 1;
        const bool inb = (dx ? x1 : x0) & (dy ? y1 : y0) & (dz ? z1 : z0);
        if (inb) {
            const float w = (dx ? wx1 : wx0) * (dy ? wy1 : wy0) * (dz ? wz1 : wz0);
            float* p = out + (basef + (long long)(dz * SZ + dy * SY + dx * SX));
            float4 v;
            v.x = w * e.x; v.y = w * e.y; v.z = w * e.z; v.w = w * e.w;
            red_add_v4(p, v);
        }
    }
}

extern "C" void kernel_launch(void* const* d_in, const int* in_sizes, int n_in,
                              void* d_out, int out_size)
{
    const float* dirs  = (const float*)d_in[0];
    const float* orig  = (const float*)d_in[1];
    const float* nearv = (const float*)d_in[2];
    const float* farv  = (const float*)d_in[3];
    const float* enc   = (const float*)d_in[4];
    const int*   gidx  = (const int*)  d_in[5];
    float* out = (float*)d_out;

    const int N = in_sizes[2];  // near has one element per ray

    cudaMemsetAsync(d_out, 0, (size_t)out_size * sizeof(float));

    dim3 block(4, ST, 1);   // 4 channel-groups x 72 samples = 288 threads
    dim3 grid(N, 1, 1);
    splat_kernel<<<grid, block>>>(dirs, orig, nearv, farv, enc, gidx, out);
}